// round 6
// baseline (speedup 1.0000x reference)
#include <cuda_runtime.h>

#define NN    8192
#define NT    512
#define EPB   16          // NT*EPB == NN
#define MAXO  300
#define NW    (NN/64)     // 128 u64 words per mask row

typedef unsigned long long u64;

// Static device scratch (no allocation). Fully rewritten every launch.
__device__ float4 g_boxes[NN];
__device__ float  g_area[NN];
__device__ int    g_sidx[NN];
__device__ __align__(16) u64 g_mask[(size_t)NN * NW];   // 8MB, self+above-diag bits

__device__ __forceinline__ void cmpex(u64& a, u64& b, bool up) {
  u64 x = a, y = b;
  if ((x > y) == up) { a = y; b = x; }
}

// ---------------------------------------------------------------------------
// Kernel A: bitonic sort of (~score_bits<<32 | idx). Blocked registers:
// thread t owns elements [t*16, t*16+16). jj<=8: register passes.
// jj in [16,256]: shfl_xor passes. jj>=512: smem passes.
// ---------------------------------------------------------------------------
__global__ __launch_bounds__(NT, 1)
void sort_kernel(const float4* __restrict__ rois,
                 const float*  __restrict__ scores,
                 float* __restrict__ out) {
  extern __shared__ u64 sk[];   // 64KB
  const int tid  = threadIdx.x;
  const int base = tid * EPB;

  for (int p = tid; p < NN; p += NT) {
    unsigned sb = __float_as_uint(scores[p]);  // scores >= 0 -> bits monotone
    sk[p] = (((u64)(~sb)) << 32) | (unsigned)p;
  }
  if (tid < MAXO) out[tid] = -1.0f;
  __syncthreads();

  u64 v[EPB];
#pragma unroll
  for (int e = 0; e < EPB; e++) v[e] = sk[base + e];

#pragma unroll
  for (int k = 2; k <= 8; k <<= 1) {
#pragma unroll
    for (int jj = k >> 1; jj; jj >>= 1) {
#pragma unroll
      for (int e = 0; e < EPB; e++) {
        int e2 = e ^ jj;
        if (e2 > e) cmpex(v[e], v[e2], ((e & k) == 0));
      }
    }
  }
  {
    bool up = ((base & 16) == 0);
#pragma unroll
    for (int jj = 8; jj; jj >>= 1)
#pragma unroll
      for (int e = 0; e < EPB; e++) {
        int e2 = e ^ jj;
        if (e2 > e) cmpex(v[e], v[e2], up);
      }
  }

  for (int k = 32; k <= NN; k <<= 1) {
    int jj = k >> 1;
    if (jj >= 512) {
#pragma unroll
      for (int e = 0; e < EPB; e++) sk[base + e] = v[e];
      __syncthreads();
      for (; jj >= 512; jj >>= 1) {
        for (int pp = tid; pp < NN / 2; pp += NT) {
          int p = ((pp & ~(jj - 1)) << 1) | (pp & (jj - 1));
          int q = p | jj;
          bool up = ((p & k) == 0);
          u64 a = sk[p], b = sk[q];
          if ((a > b) == up) { sk[p] = b; sk[q] = a; }
        }
        __syncthreads();
      }
#pragma unroll
      for (int e = 0; e < EPB; e++) v[e] = sk[base + e];
    }
    const bool up = ((base & k) == 0);
    for (; jj >= 16; jj >>= 1) {
      int s = jj >> 4;
      bool takemin = (((tid & s) == 0) == up);
#pragma unroll
      for (int e = 0; e < EPB; e++) {
        u64 o  = __shfl_xor_sync(0xFFFFFFFFu, v[e], s);
        u64 mn = (v[e] < o) ? v[e] : o;
        u64 mx = (v[e] < o) ? o : v[e];
        v[e] = takemin ? mn : mx;
      }
    }
#pragma unroll
    for (int j2 = 8; j2; j2 >>= 1)
#pragma unroll
      for (int e = 0; e < EPB; e++) {
        int e2 = e ^ j2;
        if (e2 > e) cmpex(v[e], v[e2], up);
      }
  }

#pragma unroll
  for (int e = 0; e < EPB; e++) {
    int p  = base + e;
    int id = (int)(unsigned)(v[e] & 0xFFFFFFFFull);
    g_sidx[p] = id;
    float4 bb = rois[id];
    g_boxes[p] = bb;
    g_area[p] = __fmul_rn(__fsub_rn(bb.z, bb.x), __fsub_rn(bb.w, bb.y));
  }
}

// ---------------------------------------------------------------------------
// Kernel B: suppression bitmask. Block (cb, rg): 256 threads, thread t
// handles row i = rg*256+t, computes mask word cb (cols [cb*64, cb*64+64)).
// Column boxes staged in smem (coalesced load, broadcast reads).
// Bit e set <=> j = cb*64+e >= i AND IoU(i,j) > 0.5 (diagonal bit set).
// ---------------------------------------------------------------------------
__global__ __launch_bounds__(256, 8)
void mask_kernel() {
  const int cb = blockIdx.x;
  const int t  = threadIdx.x;
  const int i  = blockIdx.y * 256 + t;
  const int jbase = cb * 64;

  __shared__ float4 cbox[64];
  __shared__ float  carea[64];
  if (t < 64) { cbox[t] = g_boxes[jbase + t]; carea[t] = g_area[jbase + t]; }
  __syncthreads();

  if (jbase + 63 < i) { g_mask[(size_t)i * NW + cb] = 0ull; return; }

  const float4 bi = g_boxes[i];
  const float  ai = g_area[i];
  u64 bits = 0;
#pragma unroll 4
  for (int e = 0; e < 64; e++) {
    float4 bj = cbox[e];
    float lx = fmaxf(bi.x, bj.x);
    float ly = fmaxf(bi.y, bj.y);
    float rx = fminf(bi.z, bj.z);
    float ry = fminf(bi.w, bj.w);
    float ww = fmaxf(__fsub_rn(rx, lx), 0.0f);
    float hh = fmaxf(__fsub_rn(ry, ly), 0.0f);
    float inter = __fmul_rn(ww, hh);
    float uni   = __fsub_rn(__fadd_rn(ai, carea[e]), inter);
    // decide (inter/uni > 0.5) exactly: margin test, IEEE-divide fallback
    float d   = __fmaf_rn(-0.5f, uni, inter);
    float tol = 1e-6f * uni;
    bool sup;
    if (d > tol)       sup = true;
    else if (d < -tol) sup = false;
    else               sup = (__fdiv_rn(inter, uni) > 0.5f);
    bits |= ((u64)sup) << e;
  }
  if (i > jbase) bits &= (~0ull) << (i - jbase);   // keep only j >= i
  g_mask[(size_t)i * NW + cb] = bits;
}

// ---------------------------------------------------------------------------
// Kernel C: single-warp greedy with depth-2 speculative row prefetch.
// Lane l owns j in [256l, 256l+256) as rem words R0..R3 (= g_mask words
// 4l..4l+3). Rows double-buffered in A/B registers; each row is consumed
// ~2 iterations after its load issues, hiding L2 latency. Speculation is
// validated by a bit test after each OR (mispredict rate ~0.3%).
// ---------------------------------------------------------------------------
__device__ __forceinline__ int findfree(u64 r0, u64 r1, u64 r2, u64 r3,
                                        int lane, int cprev) {
  const int base = lane << 8;
  int cand = NN;
#pragma unroll
  for (int q = 0; q < 4; q++) {
    u64 f = ~(q == 0 ? r0 : q == 1 ? r1 : q == 2 ? r2 : r3);
    int lo = cprev + 1 - (base + 64 * q);   // first allowed bit in this word
    if (lo >= 64) f = 0;
    else if (lo > 0) f &= (~0ull) << lo;
    if (f && cand == NN) cand = base + 64 * q + (__ffsll((long long)f) - 1);
  }
  unsigned bal = __ballot_sync(0xFFFFFFFFu, cand < NN);
  if (!bal) return NN;
  int src = __ffs(bal) - 1;                 // lowest lane == lowest j
  return __shfl_sync(0xFFFFFFFFu, cand, src);
}

#define LOADROW(p0, p1, c) do {                                          \
    const ulonglong2* _rp =                                              \
        reinterpret_cast<const ulonglong2*>(g_mask + (size_t)(c) * NW);  \
    p0 = _rp[2 * lane]; p1 = _rp[2 * lane + 1];                          \
  } while (0)

__device__ __forceinline__ bool bittest(u64 r0, u64 r1, u64 r2, u64 r3, int j) {
  int q = (j >> 6) & 3;
  u64 w = (q == 0) ? r0 : (q == 1) ? r1 : (q == 2) ? r2 : r3;
  w = __shfl_sync(0xFFFFFFFFu, w, j >> 8);
  return (w >> (j & 63)) & 1ull;
}

__global__ void greedy_kernel(float* __restrict__ out) {
  const int lane = threadIdx.x;
  u64 R0 = 0, R1 = 0, R2 = 0, R3 = 0;
  ulonglong2 A0, A1, B0, B1;

  int c0 = 0;                               // first sorted box is always kept
  LOADROW(A0, A1, c0);
  int c1 = findfree(R0, R1, R2, R3, lane, c0);
  if (c1 < NN) LOADROW(B0, B1, c1);
  int outc = 0;

  while (true) {
    // ---------------- phase A: consume buffer A ----------------
    if (lane == 0) out[outc] = (float)g_sidx[c0];
    if (++outc >= MAXO) break;
    R0 |= A0.x; R1 |= A0.y; R2 |= A1.x; R3 |= A1.y;
    if (c1 >= NN) break;
    if (bittest(R0, R1, R2, R3, c1)) {      // speculation failed (rare)
      c1 = findfree(R0, R1, R2, R3, lane, c0);
      if (c1 >= NN) break;
      LOADROW(B0, B1, c1);
    }
    {
      int c2 = findfree(R0, R1, R2, R3, lane, c1);
      c0 = c1; c1 = c2;
      if (c2 < NN) LOADROW(A0, A1, c2);     // refill freed slot
    }

    // ---------------- phase B: consume buffer B ----------------
    if (lane == 0) out[outc] = (float)g_sidx[c0];
    if (++outc >= MAXO) break;
    R0 |= B0.x; R1 |= B0.y; R2 |= B1.x; R3 |= B1.y;
    if (c1 >= NN) break;
    if (bittest(R0, R1, R2, R3, c1)) {
      c1 = findfree(R0, R1, R2, R3, lane, c0);
      if (c1 >= NN) break;
      LOADROW(A0, A1, c1);
    }
    {
      int c2 = findfree(R0, R1, R2, R3, lane, c1);
      c0 = c1; c1 = c2;
      if (c2 < NN) LOADROW(B0, B1, c2);
    }
  }
}

// ---------------------------------------------------------------------------
extern "C" void kernel_launch(void* const* d_in, const int* in_sizes, int n_in,
                              void* d_out, int out_size) {
  const void* a0 = d_in[0];
  const void* a1 = d_in[1];
  const float4* rois;
  const float*  scores;
  if (in_sizes[0] >= in_sizes[1]) { rois = (const float4*)a0; scores = (const float*)a1; }
  else                            { rois = (const float4*)a1; scores = (const float*)a0; }

  cudaFuncSetAttribute(sort_kernel, cudaFuncAttributeMaxDynamicSharedMemorySize,
                       NN * (int)sizeof(u64));
  sort_kernel<<<1, NT, NN * sizeof(u64)>>>(rois, scores, (float*)d_out);
  mask_kernel<<<dim3(NW, NN / 256), 256>>>();
  greedy_kernel<<<1, 32>>>((float*)d_out);
}

// round 7
// speedup vs baseline: 1.5485x; 1.5485x over previous
#include <cuda_runtime.h>

#define NN    8192
#define NT    512
#define EPB   16          // NT*EPB == NN
#define MAXO  300
#define NW    (NN/64)     // 128 u64 words per mask row
#define DP    16          // greedy prefetch depth (power of 2)

typedef unsigned long long u64;

// Static device scratch (no allocation). Fully rewritten every launch.
__device__ float4 g_boxes[NN];
__device__ float  g_area[NN];
__device__ int    g_sidx[NN];
__device__ __align__(16) u64 g_mask[(size_t)NN * NW];   // 8MB, self+above-diag bits

__device__ __forceinline__ void cmpex(u64& a, u64& b, bool up) {
  u64 x = a, y = b;
  if ((x > y) == up) { a = y; b = x; }
}

__device__ __forceinline__ unsigned s2u(const void* p) {
  unsigned r;
  asm("{ .reg .u64 t; cvta.to.shared.u64 t, %1; cvt.u32.u64 %0, t; }"
      : "=r"(r) : "l"(p));
  return r;
}

// ---------------------------------------------------------------------------
// Kernel A: bitonic sort of (~score_bits<<32 | idx). Blocked registers:
// thread t owns elements [t*16, t*16+16). jj<=8: register passes.
// jj in [16,256]: shfl_xor passes. jj>=512: smem passes.
// ---------------------------------------------------------------------------
__global__ __launch_bounds__(NT, 1)
void sort_kernel(const float4* __restrict__ rois,
                 const float*  __restrict__ scores,
                 float* __restrict__ out) {
  extern __shared__ u64 sk[];   // 64KB
  const int tid  = threadIdx.x;
  const int base = tid * EPB;

  for (int p = tid; p < NN; p += NT) {
    unsigned sb = __float_as_uint(scores[p]);  // scores >= 0 -> bits monotone
    sk[p] = (((u64)(~sb)) << 32) | (unsigned)p;
  }
  if (tid < MAXO) out[tid] = -1.0f;
  __syncthreads();

  u64 v[EPB];
#pragma unroll
  for (int e = 0; e < EPB; e++) v[e] = sk[base + e];

#pragma unroll
  for (int k = 2; k <= 8; k <<= 1) {
#pragma unroll
    for (int jj = k >> 1; jj; jj >>= 1) {
#pragma unroll
      for (int e = 0; e < EPB; e++) {
        int e2 = e ^ jj;
        if (e2 > e) cmpex(v[e], v[e2], ((e & k) == 0));
      }
    }
  }
  {
    bool up = ((base & 16) == 0);
#pragma unroll
    for (int jj = 8; jj; jj >>= 1)
#pragma unroll
      for (int e = 0; e < EPB; e++) {
        int e2 = e ^ jj;
        if (e2 > e) cmpex(v[e], v[e2], up);
      }
  }

  for (int k = 32; k <= NN; k <<= 1) {
    int jj = k >> 1;
    if (jj >= 512) {
#pragma unroll
      for (int e = 0; e < EPB; e++) sk[base + e] = v[e];
      __syncthreads();
      for (; jj >= 512; jj >>= 1) {
        for (int pp = tid; pp < NN / 2; pp += NT) {
          int p = ((pp & ~(jj - 1)) << 1) | (pp & (jj - 1));
          int q = p | jj;
          bool up = ((p & k) == 0);
          u64 a = sk[p], b = sk[q];
          if ((a > b) == up) { sk[p] = b; sk[q] = a; }
        }
        __syncthreads();
      }
#pragma unroll
      for (int e = 0; e < EPB; e++) v[e] = sk[base + e];
    }
    const bool up = ((base & k) == 0);
    for (; jj >= 16; jj >>= 1) {
      int s = jj >> 4;
      bool takemin = (((tid & s) == 0) == up);
#pragma unroll
      for (int e = 0; e < EPB; e++) {
        u64 o  = __shfl_xor_sync(0xFFFFFFFFu, v[e], s);
        u64 mn = (v[e] < o) ? v[e] : o;
        u64 mx = (v[e] < o) ? o : v[e];
        v[e] = takemin ? mn : mx;
      }
    }
#pragma unroll
    for (int j2 = 8; j2; j2 >>= 1)
#pragma unroll
      for (int e = 0; e < EPB; e++) {
        int e2 = e ^ j2;
        if (e2 > e) cmpex(v[e], v[e2], up);
      }
  }

#pragma unroll
  for (int e = 0; e < EPB; e++) {
    int p  = base + e;
    int id = (int)(unsigned)(v[e] & 0xFFFFFFFFull);
    g_sidx[p] = id;
    float4 bb = rois[id];
    g_boxes[p] = bb;
    g_area[p] = __fmul_rn(__fsub_rn(bb.z, bb.x), __fsub_rn(bb.w, bb.y));
  }
}

// ---------------------------------------------------------------------------
// Kernel B: suppression bitmask (unchanged from R6). Block (cb, rg): 256
// threads, thread t handles row i = rg*256+t, computes mask word cb.
// Bit e set <=> j = cb*64+e >= i AND IoU(i,j) > 0.5 (diagonal bit set).
// ---------------------------------------------------------------------------
__global__ __launch_bounds__(256, 8)
void mask_kernel() {
  const int cb = blockIdx.x;
  const int t  = threadIdx.x;
  const int i  = blockIdx.y * 256 + t;
  const int jbase = cb * 64;

  __shared__ float4 cbox[64];
  __shared__ float  carea[64];
  if (t < 64) { cbox[t] = g_boxes[jbase + t]; carea[t] = g_area[jbase + t]; }
  __syncthreads();

  if (jbase + 63 < i) { g_mask[(size_t)i * NW + cb] = 0ull; return; }

  const float4 bi = g_boxes[i];
  const float  ai = g_area[i];
  u64 bits = 0;
#pragma unroll 4
  for (int e = 0; e < 64; e++) {
    float4 bj = cbox[e];
    float lx = fmaxf(bi.x, bj.x);
    float ly = fmaxf(bi.y, bj.y);
    float rx = fminf(bi.z, bj.z);
    float ry = fminf(bi.w, bj.w);
    float ww = fmaxf(__fsub_rn(rx, lx), 0.0f);
    float hh = fmaxf(__fsub_rn(ry, ly), 0.0f);
    float inter = __fmul_rn(ww, hh);
    float uni   = __fsub_rn(__fadd_rn(ai, carea[e]), inter);
    // decide (inter/uni > 0.5) exactly: margin test, IEEE-divide fallback
    float d   = __fmaf_rn(-0.5f, uni, inter);
    float tol = 1e-6f * uni;
    bool sup;
    if (d > tol)       sup = true;
    else if (d < -tol) sup = false;
    else               sup = (__fdiv_rn(inter, uni) > 0.5f);
    bits |= ((u64)sup) << e;
  }
  if (i > jbase) bits &= (~0ull) << (i - jbase);   // keep only j >= i
  g_mask[(size_t)i * NW + cb] = bits;
}

// ---------------------------------------------------------------------------
// Kernel C: single-warp greedy, sliding-window cp.async prefetch.
// Row of EVERY scanned position is prefetched DP iterations ahead into an
// smem ring (no speculation, no mispredicts). Lane l owns columns
// [256l, 256l+256) as R0..R3 and copies/reads exactly its own 32B of each
// row, so cp.async.wait_group alone gives visibility. Suppression test uses
// a broadcast word `curw`, refreshed by one shfl on word-cross / after OR.
// ---------------------------------------------------------------------------
__global__ void greedy_kernel(float* __restrict__ out) {
  __shared__ __align__(16) u64 ring[DP][NW];   // 16KB
  const int lane = threadIdx.x;
  u64 R0 = 0, R1 = 0, R2 = 0, R3 = 0;

  // prime the pipeline: rows 0..DP-1
#pragma unroll
  for (int p = 0; p < DP; p++) {
    unsigned long long ga;
    asm("cvta.to.global.u64 %0, %1;" : "=l"(ga)
        : "l"((const void*)((const char*)(g_mask + (size_t)p * NW) + lane * 32)));
    unsigned sa = s2u(&ring[p][0]) + (unsigned)(lane * 32);
    asm volatile(
        "cp.async.cg.shared.global [%0], [%1], 16;\n\t"
        "cp.async.cg.shared.global [%2], [%3], 16;\n\t"
        "cp.async.commit_group;\n\t"
        :: "r"(sa), "l"(ga), "r"(sa + 16), "l"(ga + 16) : "memory");
  }

  int outc = 0;
  u64 curw = 0;
  int curwi = -1;

  for (int p = 0; p < NN; p++) {
    asm volatile("cp.async.wait_group %0;" :: "n"(DP - 1) : "memory");

    const int wi = p >> 6;
    if (wi != curwi) {
      u64 w = ((wi & 3) == 0) ? R0 : ((wi & 3) == 1) ? R1 : ((wi & 3) == 2) ? R2 : R3;
      curw = __shfl_sync(0xFFFFFFFFu, w, wi >> 2);
      curwi = wi;
    }

    if (!((curw >> (p & 63)) & 1ull)) {          // position p is KEPT
      if (lane == 0) out[outc] = (float)g_sidx[p];
      outc++;
      const ulonglong2* r =
          reinterpret_cast<const ulonglong2*>(&ring[p & (DP - 1)][0]);
      ulonglong2 a = r[2 * lane];
      ulonglong2 b = r[2 * lane + 1];
      R0 |= a.x; R1 |= a.y; R2 |= b.x; R3 |= b.y;
      u64 w = ((wi & 3) == 0) ? R0 : ((wi & 3) == 1) ? R1 : ((wi & 3) == 2) ? R2 : R3;
      curw = __shfl_sync(0xFFFFFFFFu, w, wi >> 2);
      if (outc >= MAXO) break;
    }

    const int np = p + DP;
    if (np < NN) {
      unsigned long long ga;
      asm("cvta.to.global.u64 %0, %1;" : "=l"(ga)
          : "l"((const void*)((const char*)(g_mask + (size_t)np * NW) + lane * 32)));
      unsigned sa = s2u(&ring[np & (DP - 1)][0]) + (unsigned)(lane * 32);
      asm volatile(
          "cp.async.cg.shared.global [%0], [%1], 16;\n\t"
          "cp.async.cg.shared.global [%2], [%3], 16;\n\t"
          :: "r"(sa), "l"(ga), "r"(sa + 16), "l"(ga + 16) : "memory");
    }
    asm volatile("cp.async.commit_group;" ::: "memory");  // one group per iter
  }
}

// ---------------------------------------------------------------------------
extern "C" void kernel_launch(void* const* d_in, const int* in_sizes, int n_in,
                              void* d_out, int out_size) {
  const void* a0 = d_in[0];
  const void* a1 = d_in[1];
  const float4* rois;
  const float*  scores;
  if (in_sizes[0] >= in_sizes[1]) { rois = (const float4*)a0; scores = (const float*)a1; }
  else                            { rois = (const float4*)a1; scores = (const float*)a0; }

  cudaFuncSetAttribute(sort_kernel, cudaFuncAttributeMaxDynamicSharedMemorySize,
                       NN * (int)sizeof(u64));
  sort_kernel<<<1, NT, NN * sizeof(u64)>>>(rois, scores, (float*)d_out);
  mask_kernel<<<dim3(NW, NN / 256), 256>>>();
  greedy_kernel<<<1, 32>>>((float*)d_out);
}